// round 11
// baseline (speedup 1.0000x reference)
#include <cuda_runtime.h>
#include <cstdint>

typedef unsigned int u32;
typedef unsigned long long u64;

#define NB 32
#define NA 49056
#define NFG 7
#define NBC (NB*NFG)
#define TOPK 200
#define DETS 200
#define NMSTHR 0.45f
#define LPB 0x3C23D70Bu      // bits(0.01f)+1 : v >= LPB <=> score > 0.01f
#define HI_BITS 0x3F800001u
#define CAP 4096
#define BUFC 640

// ---------------- scratch ----------------------------------------------------
__device__ u32 g_t1[NBC], g_t2[NBC];
__device__ int g_cnt[NBC];                    // ALWAYS left zeroed at end of call
__device__ u64 g_cand[(size_t)NBC*CAP];
__device__ float g_ks[NBC*TOPK];
__device__ int   g_ka[NBC*TOPK];
__device__ float4 g_kb[NBC*TOPK];
__device__ int   g_kc[NBC];

// ---------------- shared softmax (identical bits at every call site) ---------
__device__ __forceinline__ void softmax7(const float4* __restrict__ lg, int a, float* s7)
{
    float4 l0 = lg[a*2+0];
    float4 l1 = lg[a*2+1];
    float e[8] = {l0.x,l0.y,l0.z,l0.w,l1.x,l1.y,l1.z,l1.w};
    float mx = e[0];
#pragma unroll
    for (int i=1;i<8;i++) mx = fmaxf(mx,e[i]);
    float s = 0.f;
#pragma unroll
    for (int i=0;i<8;i++){ e[i] = expf(e[i]-mx); s += e[i]; }
    float inv = 1.0f / s;
#pragma unroll
    for (int c=0;c<7;c++) s7[c] = e[c+1]*inv;
}

__device__ __forceinline__ u32 warp_rank_search(const u32* s, int lane, int rank,
                                                u32 lo, u32 hi)
{
    while (hi - lo > 1u){
        u32 mid = lo + ((hi - lo) >> 1);
        int c = 0;
#pragma unroll
        for (int k=0;k<32;k++) c += (s[lane + (k<<5)] >= mid) ? 1 : 0;
        c = __reduce_add_sync(0xffffffffu, c);
        if (c >= rank) lo = mid; else hi = mid;
    }
    return lo;
}

// ---------------- kF: thresholds + stream logits once + buffered filter ------
__global__ __launch_bounds__(512) void kF(const float* __restrict__ logits)
{
    __shared__ union U {
        u32 sc[NFG][1024];          // phase A: samples
        u64 buf[NFG][BUFC];         // phase B: survivor buffers
        __device__ U(){}
    } sh;
    __shared__ u32 th[NFG];
    __shared__ int lcnt[NFG], lbase[NFG];

    int blk = blockIdx.x;                 // NB*12
    int b = blk / 12, ch = blk - b*12;
    int tid = threadIdx.x;
    int w = tid >> 5, lane = tid & 31;
    const float4* lg = (const float4*)(logits + (size_t)b*NA*8);

    // ---- phase A: 1024 samples -> per-class t1/t2 (same math as old kT) ----
#pragma unroll
    for (int q=0;q<2;q++){
        int j = tid + (q<<9);
        int a = (j*NA) >> 10;
        float s7[7]; softmax7(lg, a, s7);
#pragma unroll
        for (int c=0;c<7;c++) sh.sc[c][j] = __float_as_uint(s7[c]);
    }
    __syncthreads();
    if (w < NFG){
        u32 t1 = warp_rank_search(sh.sc[w], lane, 11, LPB, HI_BITS);
        if (lane == 0){ th[w] = t1; lcnt[w] = 0; }
        if (ch == 0){
            u32 t2 = warp_rank_search(sh.sc[w], lane, 41, LPB, t1 + 1u);
            if (lane == 0){ g_t1[b*NFG+w] = t1; g_t2[b*NFG+w] = t2; }
        }
    }
    __syncthreads();

    // ---- phase B: filter this block's 4096-anchor chunk ----
    int base = ch << 12;
#pragma unroll
    for (int k=0;k<8;k++){
        int a = base + tid + (k<<9);
        if (a < NA){
            float s7[7]; softmax7(lg, a, s7);
#pragma unroll
            for (int c=0;c<7;c++){
                u32 v = __float_as_uint(s7[c]);
                if (v >= th[c]){
                    u64 kk = ((u64)v << 32) | (u64)(0xFFFFFFFFu - (u32)a);
                    int p = atomicAdd(&lcnt[c], 1);
                    if (p < BUFC) sh.buf[c][p] = kk;
                    else {
                        int bc = b*NFG + c;
                        int q = atomicAdd(&g_cnt[bc], 1);
                        if (q < CAP) g_cand[(size_t)bc*CAP + q] = kk;
                    }
                }
            }
        }
    }
    __syncthreads();
    if (tid < NFG){
        int mm = min(lcnt[tid], BUFC);
        lbase[tid] = atomicAdd(&g_cnt[b*NFG + tid], mm);
    }
    __syncthreads();
#pragma unroll
    for (int c=0;c<NFG;c++){
        int mm = min(lcnt[c], BUFC);
        for (int i = tid; i < mm; i += 512){
            int q = lbase[c] + i;
            if (q < CAP) g_cand[(size_t)(b*NFG + c)*CAP + q] = sh.buf[c][i];
        }
    }
}

// ---------------- k2c: histogram select + sort + class NMS -------------------
#define K2CT 512
__global__ __launch_bounds__(K2CT) void k2c(const float* __restrict__ logits,
                                            const float* __restrict__ deltas,
                                            const float* __restrict__ dboxg)
{
    __shared__ u32 hist[1024];
    __shared__ u32 Farr[1024];
    __shared__ u32 csum[32], SC[32];
    __shared__ int sh_B, sh_red, sh_pos;
    __shared__ u32 shw[16];
    __shared__ u64 skeys[256];
    __shared__ float4 rbox[TOPK];
    __shared__ float sx0[TOPK], sy0[TOPK], sx1[TOPK], sy1[TOPK], sar[TOPK];
    __shared__ uint4 M4[TOPK*2];
    __shared__ u32 skeep[7];
    __shared__ int warpcnt[8], warpbase[8];
    u32* M = (u32*)M4;

    int bc = blockIdx.x;
    int b = bc / NFG, c = bc - b*NFG;
    int tid = threadIdx.x, lane = tid & 31, w = tid >> 5;

    int n = g_cnt[bc]; if (n > CAP) n = CAP;

    // ---- rare fallback: rescan own class slice with lower tiers ----
    if (n < TOPK){
        const float4* lg = (const float4*)(logits + (size_t)b*NA*8);
        u32 t1 = g_t1[bc], t2 = g_t2[bc];
        if (t2 < t1){
            for (int k=0;k<96;k++){
                int a = tid + (k<<9);
                if (a < NA){
                    float s7[7]; softmax7(lg, a, s7);
                    u32 v = __float_as_uint(s7[c]);
                    if (v >= t2 && v < t1){
                        int p = atomicAdd(&g_cnt[bc], 1);
                        if (p < CAP)
                            g_cand[(size_t)bc*CAP + p] =
                                ((u64)v << 32) | (u64)(0xFFFFFFFFu - (u32)a);
                    }
                }
            }
        }
        __syncthreads();
        n = g_cnt[bc]; if (n > CAP) n = CAP;
        if (n < TOPK && LPB < t2){
            for (int k=0;k<96;k++){
                int a = tid + (k<<9);
                if (a < NA){
                    float s7[7]; softmax7(lg, a, s7);
                    u32 v = __float_as_uint(s7[c]);
                    if (v >= LPB && v < t2){
                        int p = atomicAdd(&g_cnt[bc], 1);
                        if (p < CAP)
                            g_cand[(size_t)bc*CAP + p] =
                                ((u64)v << 32) | (u64)(0xFFFFFFFFu - (u32)a);
                    }
                }
            }
            __syncthreads();
            n = g_cnt[bc]; if (n > CAP) n = CAP;
        }
    }

    // ---- load candidates into registers (bounded) ----
    u64 key[8];
    int kmax = (n + K2CT - 1) >> 9;
#pragma unroll
    for (int k=0;k<8;k++){
        int i = tid + (k<<9);
        key[k] = (k < kmax && i < n) ? g_cand[(size_t)bc*CAP + i] : 0ull;
    }
    __syncthreads();    // all threads done with g_cnt/g_cand reads

    if (tid == 0){ sh_pos = 0; sh_B = -1; g_cnt[bc] = 0; }  // self-restoring init
    hist[tid] = 0; hist[tid+512] = 0;
    __syncthreads();

    // warp-aggregated smem emit into skeys
    auto emit = [&](u64 kk, bool pred){
        u32 bal = __ballot_sync(0xffffffffu, pred);
        if (pred){
            int leader = __ffs(bal) - 1;
            int basep = 0;
            if (lane == leader) basep = atomicAdd(&sh_pos, __popc(bal));
            basep = __shfl_sync(bal, basep, leader);
            int pos = basep + __popc(bal & ((1u << lane) - 1u));
            if (pos < 256) skeys[pos] = kk;
        }
    };

    int cnt;
    if (n > TOPK){
        // ---- histogram pass ----
#pragma unroll
        for (int k=0;k<8;k++){
            if (key[k]){
                u32 bkt = ((u32)(key[k] >> 32) - LPB) >> 16;
                atomicAdd(&hist[bkt], 1u);
            }
        }
        __syncthreads();
        // ---- suffix scan ----
#pragma unroll
        for (int r=0;r<2;r++){
            int bin = tid + (r<<9);
            u32 v = hist[bin];
#pragma unroll
            for (int off=1; off<32; off<<=1){
                u32 t = __shfl_down_sync(0xffffffffu, v, off);
                if (lane + off < 32) v += t;
            }
            Farr[bin] = v;
            if (lane == 0) csum[bin >> 5] = v;
        }
        __syncthreads();
        if (w == 0){
            u32 v = csum[lane];
            u32 s = v;
#pragma unroll
            for (int off=1; off<32; off<<=1){
                u32 t = __shfl_down_sync(0xffffffffu, s, off);
                if (lane + off < 32) s += t;
            }
            SC[lane] = s - v;
        }
        __syncthreads();
#pragma unroll
        for (int r=0;r<2;r++){
            int bin = tid + (r<<9);
            u32 F = SC[bin >> 5] + Farr[bin];
            if (F >= TOPK) atomicMax(&sh_B, bin);
        }
        __syncthreads();
        int B = sh_B;
        if (tid == 0) sh_red = (int)(SC[B >> 5] + Farr[B] - hist[B]);
        __syncthreads();
        int cg = sh_red;
        int hB = (int)hist[B];
        __syncthreads();

        if (cg + hB <= 256){
            u32 thr = ((u32)B << 16) + LPB;
#pragma unroll
            for (int k=0;k<8;k++)
                emit(key[k], key[k] && (u32)(key[k] >> 32) >= thr);
            __syncthreads();
            cnt = cg + hB;
        } else {
            // ---- rare deterministic path: exact value + anchor boundary ----
            auto bcount_ge = [&](u32 piv)->int{
                int cc = 0;
#pragma unroll
                for (int k=0;k<8;k++) cc += ((u32)(key[k] >> 32) >= piv) ? 1 : 0;
                cc = __reduce_add_sync(0xffffffffu, cc);
                if (lane == 0) shw[w] = (u32)cc;
                __syncthreads();
                if (tid == 0){ int t=0; for (int i=0;i<16;i++) t += (int)shw[i]; sh_red = t; }
                __syncthreads();
                int r = sh_red;
                __syncthreads();
                return r;
            };
            u32 lo = LPB, hi = HI_BITS;
            while (hi - lo > 1u){
                u32 mid = lo + ((hi - lo) >> 1);
                if (bcount_ge(mid) >= TOPK) lo = mid; else hi = mid;
            }
            u32 P = lo;
            int cg2 = bcount_ge(P + 1u);
            int krem = TOPK - cg2;
            int alo = 0, ahi = NA;
            while (ahi - alo > 1){
                int amid = alo + ((ahi - alo) >> 1);
                int cc = 0;
#pragma unroll
                for (int k=0;k<8;k++){
                    if (key[k] && (u32)(key[k] >> 32) == P){
                        int a = (int)(0xFFFFFFFFu - (u32)key[k]);
                        cc += (a < amid) ? 1 : 0;
                    }
                }
                cc = __reduce_add_sync(0xffffffffu, cc);
                if (lane == 0) shw[w] = (u32)cc;
                __syncthreads();
                if (tid == 0){ int t=0; for (int i=0;i<16;i++) t += (int)shw[i]; sh_red = t; }
                __syncthreads();
                int tot = sh_red;
                __syncthreads();
                if (tot >= krem) ahi = amid; else alo = amid;
            }
#pragma unroll
            for (int k=0;k<8;k++){
                bool pr = false;
                if (key[k]){
                    u32 sb = (u32)(key[k] >> 32);
                    int a = (int)(0xFFFFFFFFu - (u32)key[k]);
                    pr = (sb > P) || (sb == P && a < ahi);
                }
                emit(key[k], pr);
            }
            __syncthreads();
            cnt = TOPK;
        }
    } else {
#pragma unroll
        for (int k=0;k<8;k++)
            emit(key[k], key[k] != 0ull);
        __syncthreads();
        cnt = sh_pos;
        __syncthreads();
    }

    // ---- pad + descending bitonic sort of 256 (score desc, anchor asc) ----
    for (int i = tid; i < 256; i += K2CT) if (i >= cnt) skeys[i] = 0ull;
    __syncthreads();
    for (int kk=2; kk<=256; kk<<=1){
        for (int j=kk>>1; j>0; j>>=1){
            for (int i=tid; i<256; i+=K2CT){
                int ix = i ^ j;
                if (ix > i){
                    u64 a0=skeys[i], a1=skeys[ix];
                    bool up = ((i & kk) == 0);
                    if ((a0 < a1) == up){ skeys[i]=a1; skeys[ix]=a0; }
                }
            }
            __syncthreads();
        }
    }

    int m = min(cnt, TOPK);
    int nww = (m + 31) >> 5;

    // ---- decode boxes + class offset + area ----
    float off = 4.0f * (float)(c + 1);
    for (int i = tid; i < m; i += K2CT){
        int a = (int)(0xFFFFFFFFu - (u32)skeys[i]);
        float4 d  = ((const float4*)deltas)[(size_t)b*NA + a];
        float4 db = ((const float4*)dboxg)[a];
        float wdt = db.z - db.x, hgt = db.w - db.y;
        float cx = db.x + 0.5f*wdt, cy = db.y + 0.5f*hgt;
        float pcx = d.x/10.0f*wdt + cx;
        float pcy = d.y/10.0f*hgt + cy;
        float pw  = expf(d.z/5.0f)*wdt;
        float ph  = expf(d.w/5.0f)*hgt;
        float4 rb;
        rb.x = fminf(fmaxf(pcx - 0.5f*pw, 0.f), 1.f);
        rb.y = fminf(fmaxf(pcy - 0.5f*ph, 0.f), 1.f);
        rb.z = fminf(fmaxf(pcx + 0.5f*pw, 0.f), 1.f);
        rb.w = fminf(fmaxf(pcy + 0.5f*ph, 0.f), 1.f);
        rbox[i] = rb;
        float x0 = rb.x + off, y0 = rb.y + off;
        float x1 = rb.z + off, y1 = rb.w + off;
        sx0[i]=x0; sy0[i]=y0; sx1[i]=x1; sy1[i]=y1;
        sar[i] = (x1-x0)*(y1-y0);
    }
    __syncthreads();

    // ---- suppression matrix: j-boxes in regs, i broadcast, ballot ----
    {
        int wd = (w < 14) ? (w % 7) : -1;
        int half = (w < 14) ? (w / 7) : 0;
        if (wd >= 0 && wd < nww){
            int j = (wd << 5) + lane;
            bool jv = (j < m);
            float jx0 = jv ? sx0[j] : 9e9f;
            float jy0 = jv ? sy0[j] : 9e9f;
            float jx1 = jv ? sx1[j] : -9e9f;
            float jy1 = jv ? sy1[j] : -9e9f;
            float jar = jv ? sar[j] : 0.f;
            int ih = (m + 1) >> 1;
            int i0 = half ? ih : 0;
            int i1 = half ? m : ih;
            for (int i = i0; i < i1; i++){
                float xl = fmaxf(jx0, sx0[i]);
                float yt = fmaxf(jy0, sy0[i]);
                float xr = fminf(jx1, sx1[i]);
                float yb = fminf(jy1, sy1[i]);
                float inter = fmaxf(xr - xl, 0.f) * fmaxf(yb - yt, 0.f);
                float iou = inter / (jar + sar[i] - inter);
                bool sup = jv && (j > i) && (iou > NMSTHR);
                u32 bits = __ballot_sync(0xffffffffu, sup);
                if (lane == 0) M[i*8 + wd] = bits;
            }
        }
        __syncthreads();
    }

    // ---- greedy walk: 7-lane warp version with prefetch ----
    if (w == 0){
        u32 r = 0;
        u32 mwn = (lane < 7 && m > 0) ? M[lane] : 0u;
        for (int i = 0; i < m; i++){
            u32 mw = mwn;
            int i2 = (i + 1 < m) ? (i + 1) : i;
            mwn = (lane < 7) ? M[i2*8 + lane] : 0u;
            u32 ws = __shfl_sync(0xffffffffu, r, (i >> 5));
            if (!((ws >> (i & 31)) & 1u))
                r |= mw;
        }
        if (lane < 7) skeep[lane] = ~r;
    }
    __syncthreads();

    // ---- ordered compaction of kept -> global ----
    u32 bal = 0; bool kept = false;
    if (tid < 224){
        kept = (tid < m) && ((skeep[w] >> lane) & 1u);
        bal = __ballot_sync(0xffffffffu, kept);
        if (lane == 0) warpcnt[w] = __popc(bal);
    }
    __syncthreads();
    if (tid == 0){
        int s = 0;
        for (int ww=0; ww<7; ww++){ warpbase[ww] = s; s += warpcnt[ww]; }
        g_kc[bc] = s;
    }
    __syncthreads();
    if (tid < 224 && kept){
        int pos = warpbase[w] + __popc(bal & ((1u << lane) - 1u));
        g_ks[bc*TOPK + pos] = __uint_as_float((u32)(skeys[tid] >> 32));
        g_ka[bc*TOPK + pos] = (int)(0xFFFFFFFFu - (u32)skeys[tid]);
        g_kb[bc*TOPK + pos] = rbox[tid];
    }
}

// ---------------- k3: per-(b,c) rank merge -----------------------------------
__global__ __launch_bounds__(256) void k3_merge(float* __restrict__ out)
{
    __shared__ u64 sk[NFG*TOPK];
    __shared__ int scnt[NFG];
    __shared__ int rnk[TOPK];

    int bc = blockIdx.x;
    int b = bc / NFG, c = bc - b*NFG;
    int tid = threadIdx.x;

    if (tid < NFG) scnt[tid] = g_kc[b*NFG + tid];
    __syncthreads();

    for (int idx = tid; idx < NFG*TOPK; idx += 256){
        int cc = idx / TOPK;
        int p = idx - cc*TOPK;
        u64 k = 0;
        if (p < scnt[cc]){
            float s = g_ks[(b*NFG + cc)*TOPK + p];
            int   a = g_ka[(b*NFG + cc)*TOPK + p];
            k = ((u64)__float_as_uint(s) << 32)
              | ((u64)(u32)((NFG - cc) << 16))
              | (u64)(u32)(0xFFFF - a);
        }
        sk[idx] = k;
    }
    if (tid < TOPK) rnk[tid] = tid;       // base rank = within-class position
    __syncthreads();

    int mc = scnt[c];

    // 6*mc independent binary-search tasks
    for (int t = tid; t < 6*TOPK; t += 256){
        int p = t / 6;
        int o = t - p*6;
        if (p < mc){
            int c2 = o + (o >= c ? 1 : 0);
            u64 K = sk[c*TOPK + p];
            const u64* L = sk + c2*TOPK;
            int blo = 0, bhi = scnt[c2];
            while (blo < bhi){
                int mid = (blo + bhi) >> 1;
                if (L[mid] > K) blo = mid + 1; else bhi = mid;
            }
            if (blo) atomicAdd(&rnk[p], blo);
        }
    }
    __syncthreads();

    // scatter own class's entries
    for (int p = tid; p < mc; p += 256){
        int r = rnk[p];
        if (r < DETS){
            float4 bb = g_kb[(b*NFG + c)*TOPK + p];
            float  s  = __uint_as_float((u32)(sk[c*TOPK + p] >> 32));
            int base = b*DETS + r;
            out[base*4+0]=bb.x; out[base*4+1]=bb.y;
            out[base*4+2]=bb.z; out[base*4+3]=bb.w;
            out[NB*DETS*4 + base] = s;
            out[NB*DETS*5 + base] = (float)(c + 1);
        }
    }

    // zero tail [T, DETS) — ranks 0..T-1 are a permutation (keys unique)
    if (c == 0){
        int T = 0;
#pragma unroll
        for (int cc=0; cc<NFG; cc++) T += scnt[cc];
        for (int d = T + tid; d < DETS; d += 256){
            int base = b*DETS + d;
            out[base*4+0]=0.f; out[base*4+1]=0.f; out[base*4+2]=0.f; out[base*4+3]=0.f;
            out[NB*DETS*4 + base] = 0.f;
            out[NB*DETS*5 + base] = 0.f;
        }
    }
}

// ---------------- launch ----------------------------------------------------
extern "C" void kernel_launch(void* const* d_in, const int* in_sizes, int n_in,
                              void* d_out, int out_size)
{
    const float* logits = (const float*)d_in[0];
    const float* deltas = (const float*)d_in[1];
    const float* dbox   = (const float*)d_in[2];
    float* out = (float*)d_out;

    kF<<<NB*12, 512>>>(logits);
    k2c<<<NBC, K2CT>>>(logits, deltas, dbox);
    k3_merge<<<NBC, 256>>>(out);
}

// round 12
// speedup vs baseline: 1.1211x; 1.1211x over previous
#include <cuda_runtime.h>
#include <cstdint>

typedef unsigned int u32;
typedef unsigned long long u64;

#define NB 32
#define NA 49056
#define NFG 7
#define NBC (NB*NFG)
#define TOPK 200
#define DETS 200
#define NMSTHR 0.45f
#define LPB 0x3C23D70Bu      // bits(0.01f)+1 : v >= LPB <=> score > 0.01f
#define HI_BITS 0x3F800001u
#define CAP 4096
#define BUFC 768

// ---------------- scratch ----------------------------------------------------
__device__ u32 g_t1[NBC];
__device__ int g_cnt[NBC];                    // left zeroed at end of every call
__device__ u64 g_cand[(size_t)NBC*CAP];
__device__ float g_ks[NBC*TOPK];
__device__ int   g_ka[NBC*TOPK];
__device__ float4 g_kb[NBC*TOPK];
__device__ int   g_kc[NBC];

// ---------------- shared softmax (identical bits at every call site) ---------
__device__ __forceinline__ void softmax7(const float4* __restrict__ lg, int a, float* s7)
{
    float4 l0 = lg[a*2+0];
    float4 l1 = lg[a*2+1];
    float e[8] = {l0.x,l0.y,l0.z,l0.w,l1.x,l1.y,l1.z,l1.w};
    float mx = e[0];
#pragma unroll
    for (int i=1;i<8;i++) mx = fmaxf(mx,e[i]);
    float s = 0.f;
#pragma unroll
    for (int i=0;i<8;i++){ e[i] = expf(e[i]-mx); s += e[i]; }
    float inv = 1.0f / s;
#pragma unroll
    for (int c=0;c<7;c++) s7[c] = e[c+1]*inv;
}

__device__ __forceinline__ u32 warp_rank_search(const u32* s, int lane, int rank,
                                                u32 lo, u32 hi)
{
    while (hi - lo > 1u){
        u32 mid = lo + ((hi - lo) >> 1);
        int c = 0;
#pragma unroll
        for (int k=0;k<32;k++) c += (s[lane + (k<<5)] >= mid) ? 1 : 0;
        c = __reduce_add_sync(0xffffffffu, c);
        if (c >= rank) lo = mid; else hi = mid;
    }
    return lo;
}

// ---------------- kT: per-batch sampling -> emission threshold (rank 41) -----
__global__ __launch_bounds__(256) void kT(const float* __restrict__ logits)
{
    __shared__ u32 sc[NFG][1024];
    int b = blockIdx.x, tid = threadIdx.x;
    if (b == 0 && tid < NBC) g_cnt[tid] = 0;
    const float4* lg = (const float4*)(logits + (size_t)b*NA*8);
#pragma unroll
    for (int q=0;q<4;q++){
        int j = tid + (q<<8);
        int a = (j*NA) >> 10;
        float s7[7]; softmax7(lg, a, s7);
#pragma unroll
        for (int c=0;c<7;c++) sc[c][j] = __float_as_uint(s7[c]);
    }
    __syncthreads();
    int w = tid >> 5, lane = tid & 31;
    if (w < NFG){
        u32 t1 = warp_rank_search(sc[w], lane, 41, LPB, HI_BITS);
        if (lane == 0) g_t1[b*NFG+w] = t1;
    }
}

// ---------------- kF: stream logits once, buffered filter --------------------
__global__ __launch_bounds__(512) void kF(const float* __restrict__ logits)
{
    __shared__ u32 th[NFG];
    __shared__ int lcnt[NFG], lbase[NFG];
    __shared__ u64 buf[NFG][BUFC];

    int blk = blockIdx.x;                 // NB*12
    int b = blk / 12, ch = blk - b*12;
    int tid = threadIdx.x;
    if (tid < NFG){ th[tid] = g_t1[b*NFG + tid]; lcnt[tid] = 0; }
    __syncthreads();
    const float4* lg = (const float4*)(logits + (size_t)b*NA*8);
    int base = ch << 12;
#pragma unroll
    for (int k=0;k<8;k++){
        int a = base + tid + (k<<9);
        if (a < NA){
            float s7[7]; softmax7(lg, a, s7);
#pragma unroll
            for (int c=0;c<7;c++){
                u32 v = __float_as_uint(s7[c]);
                if (v >= th[c]){
                    u64 kk = ((u64)v << 32) | (u64)(0xFFFFFFFFu - (u32)a);
                    int p = atomicAdd(&lcnt[c], 1);
                    if (p < BUFC) buf[c][p] = kk;
                    else {
                        int bc = b*NFG + c;
                        int q = atomicAdd(&g_cnt[bc], 1);
                        if (q < CAP) g_cand[(size_t)bc*CAP + q] = kk;
                    }
                }
            }
        }
    }
    __syncthreads();
    if (tid < NFG){
        int mm = min(lcnt[tid], BUFC);
        lbase[tid] = atomicAdd(&g_cnt[b*NFG + tid], mm);
    }
    __syncthreads();
#pragma unroll
    for (int c=0;c<NFG;c++){
        int mm = min(lcnt[c], BUFC);
        for (int i = tid; i < mm; i += 512){
            int q = lbase[c] + i;
            if (q < CAP) g_cand[(size_t)(b*NFG + c)*CAP + q] = buf[c][i];
        }
    }
}

// ---------------- k2c: histogram select + sort + class NMS -------------------
#define K2CT 512
__global__ __launch_bounds__(K2CT) void k2c(const float* __restrict__ logits,
                                            const float* __restrict__ deltas,
                                            const float* __restrict__ dboxg)
{
    __shared__ u32 hist[1024];
    __shared__ u32 Farr[1024];
    __shared__ u32 csum[32], SC[32];
    __shared__ int sh_B, sh_red, sh_pos;
    __shared__ u32 shw[16];
    __shared__ u64 skeys[256];
    __shared__ float4 rbox[TOPK];
    __shared__ float sx0[TOPK], sy0[TOPK], sx1[TOPK], sy1[TOPK], sar[TOPK];
    __shared__ uint4 M4[TOPK*2];
    __shared__ u32 skeep[7];
    __shared__ int warpcnt[8], warpbase[8];
    u32* M = (u32*)M4;

    int bc = blockIdx.x;
    int b = bc / NFG, c = bc - b*NFG;
    int tid = threadIdx.x, lane = tid & 31, w = tid >> 5;

    int n = g_cnt[bc]; if (n > CAP) n = CAP;

    // ---- near-impossible fallback: rescan own class slice down to LPB ----
    if (n < TOPK){
        const float4* lg = (const float4*)(logits + (size_t)b*NA*8);
        u32 t1 = g_t1[bc];
        if (LPB < t1){
            for (int k=0;k<96;k++){
                int a = tid + (k<<9);
                if (a < NA){
                    float s7[7]; softmax7(lg, a, s7);
                    u32 v = __float_as_uint(s7[c]);
                    if (v >= LPB && v < t1){
                        int p = atomicAdd(&g_cnt[bc], 1);
                        if (p < CAP)
                            g_cand[(size_t)bc*CAP + p] =
                                ((u64)v << 32) | (u64)(0xFFFFFFFFu - (u32)a);
                    }
                }
            }
            __syncthreads();
            n = g_cnt[bc]; if (n > CAP) n = CAP;
        }
    }

    // ---- load candidates into registers (bounded) ----
    u64 key[8];
    int kmax = (n + K2CT - 1) >> 9;
#pragma unroll
    for (int k=0;k<8;k++){
        int i = tid + (k<<9);
        key[k] = (k < kmax && i < n) ? g_cand[(size_t)bc*CAP + i] : 0ull;
    }
    __syncthreads();

    if (tid == 0){ sh_pos = 0; sh_B = -1; g_cnt[bc] = 0; }  // self-restoring
    hist[tid] = 0; hist[tid+512] = 0;
    __syncthreads();

    // warp-aggregated smem emit into skeys
    auto emit = [&](u64 kk, bool pred){
        u32 bal = __ballot_sync(0xffffffffu, pred);
        if (pred){
            int leader = __ffs(bal) - 1;
            int basep = 0;
            if (lane == leader) basep = atomicAdd(&sh_pos, __popc(bal));
            basep = __shfl_sync(bal, basep, leader);
            int pos = basep + __popc(bal & ((1u << lane) - 1u));
            if (pos < 256) skeys[pos] = kk;
        }
    };

    int cnt;
    if (n > TOPK){
        // ---- histogram pass ----
#pragma unroll
        for (int k=0;k<8;k++){
            if (key[k]){
                u32 bkt = ((u32)(key[k] >> 32) - LPB) >> 16;
                atomicAdd(&hist[bkt], 1u);
            }
        }
        __syncthreads();
        // ---- suffix scan ----
#pragma unroll
        for (int r=0;r<2;r++){
            int bin = tid + (r<<9);
            u32 v = hist[bin];
#pragma unroll
            for (int off=1; off<32; off<<=1){
                u32 t = __shfl_down_sync(0xffffffffu, v, off);
                if (lane + off < 32) v += t;
            }
            Farr[bin] = v;
            if (lane == 0) csum[bin >> 5] = v;
        }
        __syncthreads();
        if (w == 0){
            u32 v = csum[lane];
            u32 s = v;
#pragma unroll
            for (int off=1; off<32; off<<=1){
                u32 t = __shfl_down_sync(0xffffffffu, s, off);
                if (lane + off < 32) s += t;
            }
            SC[lane] = s - v;
        }
        __syncthreads();
#pragma unroll
        for (int r=0;r<2;r++){
            int bin = tid + (r<<9);
            u32 F = SC[bin >> 5] + Farr[bin];
            if (F >= TOPK) atomicMax(&sh_B, bin);
        }
        __syncthreads();
        int B = sh_B;
        if (tid == 0) sh_red = (int)(SC[B >> 5] + Farr[B] - hist[B]);
        __syncthreads();
        int cg = sh_red;
        int hB = (int)hist[B];
        __syncthreads();

        if (cg + hB <= 256){
            u32 thr = ((u32)B << 16) + LPB;
#pragma unroll
            for (int k=0;k<8;k++)
                emit(key[k], key[k] && (u32)(key[k] >> 32) >= thr);
            __syncthreads();
            cnt = cg + hB;
        } else {
            // ---- rare deterministic path: exact value + anchor boundary ----
            auto bcount_ge = [&](u32 piv)->int{
                int cc = 0;
#pragma unroll
                for (int k=0;k<8;k++) cc += ((u32)(key[k] >> 32) >= piv) ? 1 : 0;
                cc = __reduce_add_sync(0xffffffffu, cc);
                if (lane == 0) shw[w] = (u32)cc;
                __syncthreads();
                if (tid == 0){ int t=0; for (int i=0;i<16;i++) t += (int)shw[i]; sh_red = t; }
                __syncthreads();
                int r = sh_red;
                __syncthreads();
                return r;
            };
            u32 lo = LPB, hi = HI_BITS;
            while (hi - lo > 1u){
                u32 mid = lo + ((hi - lo) >> 1);
                if (bcount_ge(mid) >= TOPK) lo = mid; else hi = mid;
            }
            u32 P = lo;
            int cg2 = bcount_ge(P + 1u);
            int krem = TOPK - cg2;
            int alo = 0, ahi = NA;
            while (ahi - alo > 1){
                int amid = alo + ((ahi - alo) >> 1);
                int cc = 0;
#pragma unroll
                for (int k=0;k<8;k++){
                    if (key[k] && (u32)(key[k] >> 32) == P){
                        int a = (int)(0xFFFFFFFFu - (u32)key[k]);
                        cc += (a < amid) ? 1 : 0;
                    }
                }
                cc = __reduce_add_sync(0xffffffffu, cc);
                if (lane == 0) shw[w] = (u32)cc;
                __syncthreads();
                if (tid == 0){ int t=0; for (int i=0;i<16;i++) t += (int)shw[i]; sh_red = t; }
                __syncthreads();
                int tot = sh_red;
                __syncthreads();
                if (tot >= krem) ahi = amid; else alo = amid;
            }
#pragma unroll
            for (int k=0;k<8;k++){
                bool pr = false;
                if (key[k]){
                    u32 sb = (u32)(key[k] >> 32);
                    int a = (int)(0xFFFFFFFFu - (u32)key[k]);
                    pr = (sb > P) || (sb == P && a < ahi);
                }
                emit(key[k], pr);
            }
            __syncthreads();
            cnt = TOPK;
        }
    } else {
#pragma unroll
        for (int k=0;k<8;k++)
            emit(key[k], key[k] != 0ull);
        __syncthreads();
        cnt = sh_pos;
        __syncthreads();
    }

    // ---- pad + descending bitonic sort of 256 (score desc, anchor asc) ----
    for (int i = tid; i < 256; i += K2CT) if (i >= cnt) skeys[i] = 0ull;
    __syncthreads();
    for (int kk=2; kk<=256; kk<<=1){
        for (int j=kk>>1; j>0; j>>=1){
            for (int i=tid; i<256; i+=K2CT){
                int ix = i ^ j;
                if (ix > i){
                    u64 a0=skeys[i], a1=skeys[ix];
                    bool up = ((i & kk) == 0);
                    if ((a0 < a1) == up){ skeys[i]=a1; skeys[ix]=a0; }
                }
            }
            __syncthreads();
        }
    }

    int m = min(cnt, TOPK);
    int nww = (m + 31) >> 5;

    // ---- decode boxes + class offset + area ----
    float off = 4.0f * (float)(c + 1);
    for (int i = tid; i < m; i += K2CT){
        int a = (int)(0xFFFFFFFFu - (u32)skeys[i]);
        float4 d  = ((const float4*)deltas)[(size_t)b*NA + a];
        float4 db = ((const float4*)dboxg)[a];
        float wdt = db.z - db.x, hgt = db.w - db.y;
        float cx = db.x + 0.5f*wdt, cy = db.y + 0.5f*hgt;
        float pcx = d.x/10.0f*wdt + cx;
        float pcy = d.y/10.0f*hgt + cy;
        float pw  = expf(d.z/5.0f)*wdt;
        float ph  = expf(d.w/5.0f)*hgt;
        float4 rb;
        rb.x = fminf(fmaxf(pcx - 0.5f*pw, 0.f), 1.f);
        rb.y = fminf(fmaxf(pcy - 0.5f*ph, 0.f), 1.f);
        rb.z = fminf(fmaxf(pcx + 0.5f*pw, 0.f), 1.f);
        rb.w = fminf(fmaxf(pcy + 0.5f*ph, 0.f), 1.f);
        rbox[i] = rb;
        float x0 = rb.x + off, y0 = rb.y + off;
        float x1 = rb.z + off, y1 = rb.w + off;
        sx0[i]=x0; sy0[i]=y0; sx1[i]=x1; sy1[i]=y1;
        sar[i] = (x1-x0)*(y1-y0);
    }
    __syncthreads();

    // ---- suppression matrix: j-boxes in regs, i broadcast, ballot ----
    {
        int wd = (w < 14) ? (w % 7) : -1;
        int half = (w < 14) ? (w / 7) : 0;
        if (wd >= 0 && wd < nww){
            int j = (wd << 5) + lane;
            bool jv = (j < m);
            float jx0 = jv ? sx0[j] : 9e9f;
            float jy0 = jv ? sy0[j] : 9e9f;
            float jx1 = jv ? sx1[j] : -9e9f;
            float jy1 = jv ? sy1[j] : -9e9f;
            float jar = jv ? sar[j] : 0.f;
            int ih = (m + 1) >> 1;
            int i0 = half ? ih : 0;
            int i1 = half ? m : ih;
            for (int i = i0; i < i1; i++){
                float xl = fmaxf(jx0, sx0[i]);
                float yt = fmaxf(jy0, sy0[i]);
                float xr = fminf(jx1, sx1[i]);
                float yb = fminf(jy1, sy1[i]);
                float inter = fmaxf(xr - xl, 0.f) * fmaxf(yb - yt, 0.f);
                float iou = inter / (jar + sar[i] - inter);
                bool sup = jv && (j > i) && (iou > NMSTHR);
                u32 bits = __ballot_sync(0xffffffffu, sup);
                if (lane == 0) M[i*8 + wd] = bits;
            }
        }
        __syncthreads();
    }

    // ---- greedy walk: 7-lane warp version with prefetch ----
    if (w == 0){
        u32 r = 0;
        u32 mwn = (lane < 7 && m > 0) ? M[lane] : 0u;
        for (int i = 0; i < m; i++){
            u32 mw = mwn;
            int i2 = (i + 1 < m) ? (i + 1) : i;
            mwn = (lane < 7) ? M[i2*8 + lane] : 0u;
            u32 ws = __shfl_sync(0xffffffffu, r, (i >> 5));
            if (!((ws >> (i & 31)) & 1u))
                r |= mw;
        }
        if (lane < 7) skeep[lane] = ~r;
    }
    __syncthreads();

    // ---- ordered compaction of kept -> global ----
    u32 bal = 0; bool kept = false;
    if (tid < 224){
        kept = (tid < m) && ((skeep[w] >> lane) & 1u);
        bal = __ballot_sync(0xffffffffu, kept);
        if (lane == 0) warpcnt[w] = __popc(bal);
    }
    __syncthreads();
    if (tid == 0){
        int s = 0;
        for (int ww=0; ww<7; ww++){ warpbase[ww] = s; s += warpcnt[ww]; }
        g_kc[bc] = s;
    }
    __syncthreads();
    if (tid < 224 && kept){
        int pos = warpbase[w] + __popc(bal & ((1u << lane) - 1u));
        g_ks[bc*TOPK + pos] = __uint_as_float((u32)(skeys[tid] >> 32));
        g_ka[bc*TOPK + pos] = (int)(0xFFFFFFFFu - (u32)skeys[tid]);
        g_kb[bc*TOPK + pos] = rbox[tid];
    }
}

// ---------------- k3: per-(b,c) rank merge -----------------------------------
__global__ __launch_bounds__(256) void k3_merge(float* __restrict__ out)
{
    __shared__ u64 sk[NFG*TOPK];
    __shared__ int scnt[NFG];
    __shared__ int rnk[TOPK];

    int bc = blockIdx.x;
    int b = bc / NFG, c = bc - b*NFG;
    int tid = threadIdx.x;

    if (tid < NFG) scnt[tid] = g_kc[b*NFG + tid];
    __syncthreads();

    for (int idx = tid; idx < NFG*TOPK; idx += 256){
        int cc = idx / TOPK;
        int p = idx - cc*TOPK;
        u64 k = 0;
        if (p < scnt[cc]){
            float s = g_ks[(b*NFG + cc)*TOPK + p];
            int   a = g_ka[(b*NFG + cc)*TOPK + p];
            k = ((u64)__float_as_uint(s) << 32)
              | ((u64)(u32)((NFG - cc) << 16))
              | (u64)(u32)(0xFFFF - a);
        }
        sk[idx] = k;
    }
    if (tid < TOPK) rnk[tid] = tid;
    __syncthreads();

    int mc = scnt[c];

    for (int t = tid; t < 6*TOPK; t += 256){
        int p = t / 6;
        int o = t - p*6;
        if (p < mc){
            int c2 = o + (o >= c ? 1 : 0);
            u64 K = sk[c*TOPK + p];
            const u64* L = sk + c2*TOPK;
            int blo = 0, bhi = scnt[c2];
            while (blo < bhi){
                int mid = (blo + bhi) >> 1;
                if (L[mid] > K) blo = mid + 1; else bhi = mid;
            }
            if (blo) atomicAdd(&rnk[p], blo);
        }
    }
    __syncthreads();

    for (int p = tid; p < mc; p += 256){
        int r = rnk[p];
        if (r < DETS){
            float4 bb = g_kb[(b*NFG + c)*TOPK + p];
            float  s  = __uint_as_float((u32)(sk[c*TOPK + p] >> 32));
            int base = b*DETS + r;
            out[base*4+0]=bb.x; out[base*4+1]=bb.y;
            out[base*4+2]=bb.z; out[base*4+3]=bb.w;
            out[NB*DETS*4 + base] = s;
            out[NB*DETS*5 + base] = (float)(c + 1);
        }
    }

    if (c == 0){
        int T = 0;
#pragma unroll
        for (int cc=0; cc<NFG; cc++) T += scnt[cc];
        for (int d = T + tid; d < DETS; d += 256){
            int base = b*DETS + d;
            out[base*4+0]=0.f; out[base*4+1]=0.f; out[base*4+2]=0.f; out[base*4+3]=0.f;
            out[NB*DETS*4 + base] = 0.f;
            out[NB*DETS*5 + base] = 0.f;
        }
    }
}

// ---------------- launch ----------------------------------------------------
extern "C" void kernel_launch(void* const* d_in, const int* in_sizes, int n_in,
                              void* d_out, int out_size)
{
    const float* logits = (const float*)d_in[0];
    const float* deltas = (const float*)d_in[1];
    const float* dbox   = (const float*)d_in[2];
    float* out = (float*)d_out;

    kT<<<NB, 256>>>(logits);
    kF<<<NB*12, 512>>>(logits);
    k2c<<<NBC, K2CT>>>(logits, deltas, dbox);
    k3_merge<<<NBC, 256>>>(out);
}